// round 15
// baseline (speedup 1.0000x reference)
#include <cuda_runtime.h>
#include <cuda_fp16.h>
#include <math.h>

#define NTOK 8192
#define DIM  1024
#define MT   64            // A rows per CTA tile
#define NTILE 128          // B rows per CTA tile
#define KT   64            // k-tile depth (fp16 elements)
#define BPADE 72           // smem row stride in elements (144B)
#define ARR_A (MT * BPADE * 2)      // 9216
#define ARR_B (NTILE * BPADE * 2)   // 18432
#define STAGE_BYTES (ARR_A + ARR_B) // 27648
#define NSTAGE 3
#define NTHR 256
#define SMEM_GEMM (NSTAGE * STAGE_BYTES)   // 82944

// ---------------------------------------------------------------------------
// Scratch (static device globals) — all operands single fp16 limb
// ---------------------------------------------------------------------------
__device__ __half g_xh[(size_t)NTOK * DIM];
__device__ __half g_Wh[3][(size_t)DIM * DIM];
__device__ __half g_Qh[(size_t)NTOK * DIM];
__device__ __half g_Kh[(size_t)NTOK * DIM];
__device__ __half g_Vth[(size_t)DIM * NTOK];                      // [dim][token]
__device__ __half g_Ph[(size_t)NTOK * NTOK];                      // P~ = exp(score)
__device__ float g_l[NTOK];                                       // row sums of P~
__device__ float g_Opart[2][(size_t)NTOK * DIM];                  // split-K partials

// ---------------------------------------------------------------------------
// helpers
// ---------------------------------------------------------------------------
__device__ __forceinline__ unsigned smem_u32(const void* p) {
    return (unsigned)__cvta_generic_to_shared(p);
}
__device__ __forceinline__ void cpa16(unsigned s, const void* g) {
    asm volatile("cp.async.cg.shared.global [%0],[%1],16;" :: "r"(s), "l"(g));
}
__device__ __forceinline__ void cpa_commit() {
    asm volatile("cp.async.commit_group;" ::: "memory");
}
__device__ __forceinline__ void cpa_wait0() {
    asm volatile("cp.async.wait_group 0;" ::: "memory");
}
__device__ __forceinline__ void cpa_wait1() {
    asm volatile("cp.async.wait_group 1;" ::: "memory");
}
__device__ __forceinline__ void ldsm4(unsigned r[4], unsigned addr) {
    asm volatile("ldmatrix.sync.aligned.m8n8.x4.shared.b16 {%0,%1,%2,%3},[%4];"
                 : "=r"(r[0]), "=r"(r[1]), "=r"(r[2]), "=r"(r[3]) : "r"(addr));
}
__device__ __forceinline__ void mma_f16(float c[4], const unsigned a[4], const unsigned b[2]) {
    asm volatile("mma.sync.aligned.m16n8k16.row.col.f32.f16.f16.f32 "
                 "{%0,%1,%2,%3},{%4,%5,%6,%7},{%8,%9},{%0,%1,%2,%3};"
                 : "+f"(c[0]), "+f"(c[1]), "+f"(c[2]), "+f"(c[3])
                 : "r"(a[0]), "r"(a[1]), "r"(a[2]), "r"(a[3]), "r"(b[0]), "r"(b[1]));
}

// ---------------------------------------------------------------------------
// fragment load for one k16 slice; warp tile 32x32
// ---------------------------------------------------------------------------
__device__ __forceinline__ void load_frags(
    const char* sb, int kk, int lane, int wm, int wn,
    unsigned ah[2][4], unsigned bh[2][4])
{
    const __half (*Ah)[BPADE] = (const __half(*)[BPADE])(sb);
    const __half (*Bh)[BPADE] = (const __half(*)[BPADE])(sb + ARR_A);

    int arow = (lane & 7) + ((lane >> 3) & 1) * 8;
    int acol = kk + (lane >> 4) * 8;
#pragma unroll
    for (int mi = 0; mi < 2; mi++)
        ldsm4(ah[mi], smem_u32(&Ah[wm * 32 + mi * 16 + arow][acol]));
    int brow = (lane & 7) + ((lane >> 4) & 1) * 8;
    int bcol = kk + ((lane >> 3) & 1) * 8;
#pragma unroll
    for (int p = 0; p < 2; p++)
        ldsm4(bh[p], smem_u32(&Bh[wn * 32 + p * 16 + brow][bcol]));
}

// one 64x128xKT tile, frag double-buffered across the 4 k16 slices
__device__ __forceinline__ void mma_tile(const char* sb, int lane, int wm, int wn,
                                         float acc[2][4][4])
{
    unsigned ah[2][2][4], bh[2][2][4];
    load_frags(sb, 0, lane, wm, wn, ah[0], bh[0]);
#pragma unroll
    for (int s = 0; s < KT / 16; s++) {
        if (s + 1 < KT / 16)
            load_frags(sb, (s + 1) * 16, lane, wm, wn, ah[(s + 1) & 1], bh[(s + 1) & 1]);
#pragma unroll
        for (int mi = 0; mi < 2; mi++)
#pragma unroll
            for (int ni = 0; ni < 4; ni++)
                mma_f16(acc[mi][ni], ah[s & 1][mi], &bh[s & 1][ni >> 1][(ni & 1) * 2]);
    }
}

// ---------------------------------------------------------------------------
// 3-stage pipelined mainloop. A 64 rows at rowBase, B 128 rows at colBase.
// ---------------------------------------------------------------------------
template <int KITERS>
__device__ __forceinline__ void gemm_core(
    const __half* __restrict__ Agh, int sA,
    const __half* __restrict__ Bgh, int sB,
    int rowBase, int colBase, char* smem, float acc[2][4][4])
{
    int tid = threadIdx.x;
    int lane = tid & 31, warp = tid >> 5, wm = warp >> 2, wn = warp & 3;
    unsigned sbase = smem_u32(smem);

#pragma unroll
    for (int pr = 0; pr < 2; pr++) {
        unsigned off = pr * STAGE_BYTES;
        int koff = pr * KT;
#pragma unroll
        for (int j = 0; j < 2; j++) {
            int idx = tid + j * NTHR;
            int row = idx >> 3, col = (idx & 7) * 8;
            cpa16(sbase + off + (row * BPADE + col) * 2,
                  Agh + (size_t)(rowBase + row) * sA + koff + col);
        }
#pragma unroll
        for (int j = 0; j < 4; j++) {
            int idx = tid + j * NTHR;
            int row = idx >> 3, col = (idx & 7) * 8;
            cpa16(sbase + off + ARR_A + (row * BPADE + col) * 2,
                  Bgh + (size_t)(colBase + row) * sB + koff + col);
        }
        cpa_commit();
    }

    for (int it = 0; it < KITERS; it++) {
        if (it == KITERS - 1) cpa_wait0(); else cpa_wait1();
        __syncthreads();
        if (it + 2 < KITERS) {
            unsigned off = ((it + 2) % NSTAGE) * STAGE_BYTES;
            int koff = (it + 2) * KT;
#pragma unroll
            for (int j = 0; j < 2; j++) {
                int idx = tid + j * NTHR;
                int row = idx >> 3, col = (idx & 7) * 8;
                cpa16(sbase + off + (row * BPADE + col) * 2,
                      Agh + (size_t)(rowBase + row) * sA + koff + col);
            }
#pragma unroll
            for (int j = 0; j < 4; j++) {
                int idx = tid + j * NTHR;
                int row = idx >> 3, col = (idx & 7) * 8;
                cpa16(sbase + off + ARR_A + (row * BPADE + col) * 2,
                      Bgh + (size_t)(colBase + row) * sB + koff + col);
            }
            cpa_commit();
        }
        mma_tile(smem + (it % NSTAGE) * STAGE_BYTES, lane, wm, wn, acc);
    }
}

// ---------------------------------------------------------------------------
// fp32 -> fp16 converts
// ---------------------------------------------------------------------------
__global__ __launch_bounds__(256) void cvt_x_kernel(const float* __restrict__ src)
{
    int i = (blockIdx.x * 256 + threadIdx.x) * 4;
    float4 v = *(const float4*)(src + i);
    ((__half2*)(g_xh + i))[0] = __floats2half2_rn(v.x, v.y);
    ((__half2*)(g_xh + i))[1] = __floats2half2_rn(v.z, v.w);
}

__global__ __launch_bounds__(256) void cvt_w_kernel(
    const float* __restrict__ Wq, const float* __restrict__ Wk,
    const float* __restrict__ Wv)
{
    int z = blockIdx.y;
    const float* src = (z == 0) ? Wq : (z == 1) ? Wk : Wv;
    __half* dst = g_Wh[z];
    int i = (blockIdx.x * 256 + threadIdx.x) * 4;
    float4 v = *(const float4*)(src + i);
    ((__half2*)(dst + i))[0] = __floats2half2_rn(v.x, v.y);
    ((__half2*)(dst + i))[1] = __floats2half2_rn(v.z, v.w);
}

// zero row-sum accumulators (must run every launch: atomics accumulate)
__global__ __launch_bounds__(1024) void zero_l_kernel()
{
    g_l[blockIdx.x * 1024 + threadIdx.x] = 0.0f;
}

// final reduce: O = Opart[0] + Opart[1]
__global__ __launch_bounds__(256) void reduce_o_kernel(float* __restrict__ O)
{
    int i = (blockIdx.x * 256 + threadIdx.x) * 4;
    float4 a = *(const float4*)(&g_Opart[0][i]);
    float4 b = *(const float4*)(&g_Opart[1][i]);
    float4 o;
    o.x = a.x + b.x; o.y = a.y + b.y; o.z = a.z + b.z; o.w = a.w + b.w;
    *(float4*)(O + i) = o;
}

// ---------------------------------------------------------------------------
// QKV: out = x @ W^T + b.  z=0: Q; z=1: K; z=2: V transposed.
// grid (128, 8, 3), block 256
// ---------------------------------------------------------------------------
__global__ __launch_bounds__(NTHR, 2) void qkv_mma(
    const float* __restrict__ bq, const float* __restrict__ bk,
    const float* __restrict__ bv)
{
    extern __shared__ char smem[];
    int z = blockIdx.z;
    const float* bias = (z == 0) ? bq : (z == 1) ? bk : bv;

    int tid = threadIdx.x, lane = tid & 31, warp = tid >> 5;
    int wm = warp >> 2, wn = warp & 3;
    int rowBase = blockIdx.x * MT, colBase = blockIdx.y * NTILE;

    float acc[2][4][4] = {};
    gemm_core<DIM / KT>(g_xh, DIM, g_Wh[z], DIM, rowBase, colBase, smem, acc);

    if (z < 2) {
        __half* oh = (z == 0) ? g_Qh : g_Kh;
#pragma unroll
        for (int mi = 0; mi < 2; mi++)
#pragma unroll
            for (int ni = 0; ni < 4; ni++) {
                int r = rowBase + wm * 32 + mi * 16 + (lane >> 2);
                int c = colBase + wn * 32 + ni * 8 + (lane & 3) * 2;
                float b0 = bias[c], b1 = bias[c + 1];
#pragma unroll
                for (int hr = 0; hr < 2; hr++) {
                    size_t o = (size_t)(r + hr * 8) * DIM + c;
                    *(__half2*)(oh + o) = __floats2half2_rn(
                        acc[mi][ni][hr * 2] + b0, acc[mi][ni][hr * 2 + 1] + b1);
                }
            }
    } else {
        // V: transpose via smem, store [dim][token]
        __syncthreads();  // done with mainloop buffers
        __half (*Th)[BPADE] = (__half(*)[BPADE])(smem);   // [128 dims][64 tokens + pad]
#pragma unroll
        for (int mi = 0; mi < 2; mi++)
#pragma unroll
            for (int ni = 0; ni < 4; ni++) {
                int rL = wm * 32 + mi * 16 + (lane >> 2);
                int cL = wn * 32 + ni * 8 + (lane & 3) * 2;
                float b0 = bias[colBase + cL], b1 = bias[colBase + cL + 1];
#pragma unroll
                for (int hr = 0; hr < 2; hr++) {
                    Th[cL][rL + hr * 8]     = __float2half_rn(acc[mi][ni][hr * 2] + b0);
                    Th[cL + 1][rL + hr * 8] = __float2half_rn(acc[mi][ni][hr * 2 + 1] + b1);
                }
            }
        __syncthreads();
#pragma unroll
        for (int j = 0; j < 4; j++) {
            int idx = j * NTHR + tid;
            int cRow = idx >> 3, ch = (idx & 7) * 8;
            float4 vh = *(float4*)&Th[cRow][ch];
            *(float4*)(g_Vth + (size_t)(colBase + cRow) * NTOK + rowBase + ch) = vh;
        }
    }
}

// ---------------------------------------------------------------------------
// Scores fused with exp: P~ = exp((Q K^T)/32 - |dt|/86400), row sums -> g_l.
// grid (128, 64), block 256
// ---------------------------------------------------------------------------
__global__ __launch_bounds__(NTHR, 2) void scores_mma(const float* __restrict__ ts)
{
    extern __shared__ char smem[];
    int tid = threadIdx.x, lane = tid & 31, warp = tid >> 5;
    int wm = warp >> 2, wn = warp & 3;
    int rowBase = blockIdx.x * MT, colBase = blockIdx.y * NTILE;

    float acc[2][4][4] = {};
    gemm_core<DIM / KT>(g_Qh, DIM, g_Kh, DIM, rowBase, colBase, smem, acc);

    const float inv_scale = 1.0f / 32.0f;
    const float inv_T = 1.0f / 86400.0f;

#pragma unroll
    for (int mi = 0; mi < 2; mi++) {
        int r = rowBase + wm * 32 + mi * 16 + (lane >> 2);
        float t_r0 = ts[r], t_r1 = ts[r + 8];
        float sum0 = 0.0f, sum1 = 0.0f;
#pragma unroll
        for (int ni = 0; ni < 4; ni++) {
            int c = colBase + wn * 32 + ni * 8 + (lane & 3) * 2;
            float tc0 = ts[c], tc1 = ts[c + 1];
            float p00 = __expf(acc[mi][ni][0] * inv_scale - fabsf(t_r0 - tc0) * inv_T);
            float p01 = __expf(acc[mi][ni][1] * inv_scale - fabsf(t_r0 - tc1) * inv_T);
            float p10 = __expf(acc[mi][ni][2] * inv_scale - fabsf(t_r1 - tc0) * inv_T);
            float p11 = __expf(acc[mi][ni][3] * inv_scale - fabsf(t_r1 - tc1) * inv_T);
            sum0 += p00 + p01;
            sum1 += p10 + p11;
            *(__half2*)(g_Ph + (size_t)r * NTOK + c) = __floats2half2_rn(p00, p01);
            *(__half2*)(g_Ph + (size_t)(r + 8) * NTOK + c) = __floats2half2_rn(p10, p11);
        }
        sum0 += __shfl_xor_sync(0xffffffff, sum0, 1);
        sum0 += __shfl_xor_sync(0xffffffff, sum0, 2);
        sum1 += __shfl_xor_sync(0xffffffff, sum1, 1);
        sum1 += __shfl_xor_sync(0xffffffff, sum1, 2);
        if ((lane & 3) == 0) {
            atomicAdd(&g_l[r], sum0);
            atomicAdd(&g_l[r + 8], sum1);
        }
    }
}

// ---------------------------------------------------------------------------
// Output split-K: Opart[z] = diag(1/l) P~[:, zK/2:(z+1)K/2] @ V[zK/2:...]
// grid (128, 8, 2), block 256
// ---------------------------------------------------------------------------
__global__ __launch_bounds__(NTHR, 2) void out_mma()
{
    extern __shared__ char smem[];
    int tid = threadIdx.x, lane = tid & 31, warp = tid >> 5;
    int wm = warp >> 2, wn = warp & 3;
    int rowBase = blockIdx.x * MT, colBase = blockIdx.y * NTILE;
    int kBase = blockIdx.z * (NTOK / 2);
    float* Op = g_Opart[blockIdx.z];

    float acc[2][4][4] = {};
    gemm_core<NTOK / 2 / KT>(g_Ph + kBase, NTOK, g_Vth + kBase, NTOK,
                             rowBase, colBase, smem, acc);

#pragma unroll
    for (int mi = 0; mi < 2; mi++) {
        int r = rowBase + wm * 32 + mi * 16 + (lane >> 2);
        float i0 = 1.0f / g_l[r], i1 = 1.0f / g_l[r + 8];
#pragma unroll
        for (int ni = 0; ni < 4; ni++) {
            int c = colBase + wn * 32 + ni * 8 + (lane & 3) * 2;
            *(float2*)(Op + (size_t)r * DIM + c) =
                make_float2(acc[mi][ni][0] * i0, acc[mi][ni][1] * i0);
            *(float2*)(Op + (size_t)(r + 8) * DIM + c) =
                make_float2(acc[mi][ni][2] * i1, acc[mi][ni][3] * i1);
        }
    }
}

// ---------------------------------------------------------------------------
extern "C" void kernel_launch(void* const* d_in, const int* in_sizes, int n_in,
                              void* d_out, int out_size)
{
    const float* x  = (const float*)d_in[0];
    const float* ts = (const float*)d_in[1];
    const float* Wq = (const float*)d_in[2];
    const float* bq = (const float*)d_in[3];
    const float* Wk = (const float*)d_in[4];
    const float* bk = (const float*)d_in[5];
    const float* Wv = (const float*)d_in[6];
    const float* bv = (const float*)d_in[7];
    float* out = (float*)d_out;

    cudaFuncSetAttribute(qkv_mma,    cudaFuncAttributeMaxDynamicSharedMemorySize, SMEM_GEMM);
    cudaFuncSetAttribute(scores_mma, cudaFuncAttributeMaxDynamicSharedMemorySize, SMEM_GEMM);
    cudaFuncSetAttribute(out_mma,    cudaFuncAttributeMaxDynamicSharedMemorySize, SMEM_GEMM);

    const size_t ND = (size_t)NTOK * DIM, DD = (size_t)DIM * DIM;
    cvt_x_kernel<<<(int)(ND / 1024), 256>>>(x);
    cvt_w_kernel<<<dim3((int)(DD / 1024), 3), 256>>>(Wq, Wk, Wv);
    zero_l_kernel<<<NTOK / 1024, 1024>>>();

    qkv_mma<<<dim3(NTOK / MT, DIM / NTILE, 3), NTHR, SMEM_GEMM>>>(bq, bk, bv);
    scores_mma<<<dim3(NTOK / MT, NTOK / NTILE), NTHR, SMEM_GEMM>>>(ts);
    out_mma<<<dim3(NTOK / MT, DIM / NTILE, 2), NTHR, SMEM_GEMM>>>();
    reduce_o_kernel<<<(int)(ND / 1024), 256>>>(out);
}

// round 16
// speedup vs baseline: 1.0304x; 1.0304x over previous
#include <cuda_runtime.h>
#include <cuda_fp16.h>
#include <math.h>

#define NTOK 8192
#define DIM  1024
#define MT   64            // A rows per CTA tile
#define NTILE 128          // B rows per CTA tile
#define KT   64            // k-tile depth (fp16 elements)
#define BPADE 72           // smem row stride in elements (144B)
#define ARR_A (MT * BPADE * 2)      // 9216
#define ARR_B (NTILE * BPADE * 2)   // 18432
#define STAGE_BYTES (ARR_A + ARR_B) // 27648
#define NSTAGE 3
#define NTHR 256
#define SMEM_GEMM (NSTAGE * STAGE_BYTES)   // 82944

// ---------------------------------------------------------------------------
// Scratch (static device globals) — all operands single fp16 limb
// ---------------------------------------------------------------------------
__device__ __half g_xh[(size_t)NTOK * DIM];
__device__ __half g_Wh[3][(size_t)DIM * DIM];
__device__ __half g_Qh[(size_t)NTOK * DIM];
__device__ __half g_Kh[(size_t)NTOK * DIM];
__device__ __half g_Vth[(size_t)DIM * NTOK];                      // [dim][token]
__device__ __half g_Ph[(size_t)NTOK * NTOK];                      // P~ = exp(score)
__device__ float g_l[NTOK];                                       // row sums of P~

// ---------------------------------------------------------------------------
// helpers
// ---------------------------------------------------------------------------
__device__ __forceinline__ unsigned smem_u32(const void* p) {
    return (unsigned)__cvta_generic_to_shared(p);
}
__device__ __forceinline__ void cpa16(unsigned s, const void* g) {
    asm volatile("cp.async.cg.shared.global [%0],[%1],16;" :: "r"(s), "l"(g));
}
__device__ __forceinline__ void cpa_commit() {
    asm volatile("cp.async.commit_group;" ::: "memory");
}
__device__ __forceinline__ void cpa_wait0() {
    asm volatile("cp.async.wait_group 0;" ::: "memory");
}
__device__ __forceinline__ void cpa_wait1() {
    asm volatile("cp.async.wait_group 1;" ::: "memory");
}
__device__ __forceinline__ void ldsm4(unsigned r[4], unsigned addr) {
    asm volatile("ldmatrix.sync.aligned.m8n8.x4.shared.b16 {%0,%1,%2,%3},[%4];"
                 : "=r"(r[0]), "=r"(r[1]), "=r"(r[2]), "=r"(r[3]) : "r"(addr));
}
__device__ __forceinline__ void mma_f16(float c[4], const unsigned a[4], const unsigned b[2]) {
    asm volatile("mma.sync.aligned.m16n8k16.row.col.f32.f16.f16.f32 "
                 "{%0,%1,%2,%3},{%4,%5,%6,%7},{%8,%9},{%0,%1,%2,%3};"
                 : "+f"(c[0]), "+f"(c[1]), "+f"(c[2]), "+f"(c[3])
                 : "r"(a[0]), "r"(a[1]), "r"(a[2]), "r"(a[3]), "r"(b[0]), "r"(b[1]));
}

// ---------------------------------------------------------------------------
// fragment load for one k16 slice; warp tile 32x32
// ---------------------------------------------------------------------------
__device__ __forceinline__ void load_frags(
    const char* sb, int kk, int lane, int wm, int wn,
    unsigned ah[2][4], unsigned bh[2][4])
{
    const __half (*Ah)[BPADE] = (const __half(*)[BPADE])(sb);
    const __half (*Bh)[BPADE] = (const __half(*)[BPADE])(sb + ARR_A);

    int arow = (lane & 7) + ((lane >> 3) & 1) * 8;
    int acol = kk + (lane >> 4) * 8;
#pragma unroll
    for (int mi = 0; mi < 2; mi++)
        ldsm4(ah[mi], smem_u32(&Ah[wm * 32 + mi * 16 + arow][acol]));
    int brow = (lane & 7) + ((lane >> 4) & 1) * 8;
    int bcol = kk + ((lane >> 3) & 1) * 8;
#pragma unroll
    for (int p = 0; p < 2; p++)
        ldsm4(bh[p], smem_u32(&Bh[wn * 32 + p * 16 + brow][bcol]));
}

// one 64x128xKT tile, frag double-buffered across the 4 k16 slices
__device__ __forceinline__ void mma_tile(const char* sb, int lane, int wm, int wn,
                                         float acc[2][4][4])
{
    unsigned ah[2][2][4], bh[2][2][4];
    load_frags(sb, 0, lane, wm, wn, ah[0], bh[0]);
#pragma unroll
    for (int s = 0; s < KT / 16; s++) {
        if (s + 1 < KT / 16)
            load_frags(sb, (s + 1) * 16, lane, wm, wn, ah[(s + 1) & 1], bh[(s + 1) & 1]);
#pragma unroll
        for (int mi = 0; mi < 2; mi++)
#pragma unroll
            for (int ni = 0; ni < 4; ni++)
                mma_f16(acc[mi][ni], ah[s & 1][mi], &bh[s & 1][ni >> 1][(ni & 1) * 2]);
    }
}

// ---------------------------------------------------------------------------
// 3-stage pipelined mainloop. A 64 rows at rowBase, B 128 rows at colBase.
// ---------------------------------------------------------------------------
template <int KITERS>
__device__ __forceinline__ void gemm_core(
    const __half* __restrict__ Agh, int sA,
    const __half* __restrict__ Bgh, int sB,
    int rowBase, int colBase, char* smem, float acc[2][4][4])
{
    int tid = threadIdx.x;
    int lane = tid & 31, warp = tid >> 5, wm = warp >> 2, wn = warp & 3;
    unsigned sbase = smem_u32(smem);

#pragma unroll
    for (int pr = 0; pr < 2; pr++) {
        unsigned off = pr * STAGE_BYTES;
        int koff = pr * KT;
#pragma unroll
        for (int j = 0; j < 2; j++) {
            int idx = tid + j * NTHR;
            int row = idx >> 3, col = (idx & 7) * 8;
            cpa16(sbase + off + (row * BPADE + col) * 2,
                  Agh + (size_t)(rowBase + row) * sA + koff + col);
        }
#pragma unroll
        for (int j = 0; j < 4; j++) {
            int idx = tid + j * NTHR;
            int row = idx >> 3, col = (idx & 7) * 8;
            cpa16(sbase + off + ARR_A + (row * BPADE + col) * 2,
                  Bgh + (size_t)(colBase + row) * sB + koff + col);
        }
        cpa_commit();
    }

    for (int it = 0; it < KITERS; it++) {
        if (it == KITERS - 1) cpa_wait0(); else cpa_wait1();
        __syncthreads();
        if (it + 2 < KITERS) {
            unsigned off = ((it + 2) % NSTAGE) * STAGE_BYTES;
            int koff = (it + 2) * KT;
#pragma unroll
            for (int j = 0; j < 2; j++) {
                int idx = tid + j * NTHR;
                int row = idx >> 3, col = (idx & 7) * 8;
                cpa16(sbase + off + (row * BPADE + col) * 2,
                      Agh + (size_t)(rowBase + row) * sA + koff + col);
            }
#pragma unroll
            for (int j = 0; j < 4; j++) {
                int idx = tid + j * NTHR;
                int row = idx >> 3, col = (idx & 7) * 8;
                cpa16(sbase + off + ARR_A + (row * BPADE + col) * 2,
                      Bgh + (size_t)(colBase + row) * sB + koff + col);
            }
            cpa_commit();
        }
        mma_tile(smem + (it % NSTAGE) * STAGE_BYTES, lane, wm, wn, acc);
    }
}

// ---------------------------------------------------------------------------
// fused preprocessing: fp32->fp16 convert of x and the 3 W's, plus g_l zero.
// grid covers (ND + 3*DD)/4 threads.
// ---------------------------------------------------------------------------
__global__ __launch_bounds__(256) void preprocess_kernel(
    const float* __restrict__ x,
    const float* __restrict__ Wq, const float* __restrict__ Wk,
    const float* __restrict__ Wv)
{
    const size_t ND = (size_t)NTOK * DIM, DD = (size_t)DIM * DIM;
    size_t gid = (size_t)blockIdx.x * 256 + threadIdx.x;
    if (gid < NTOK) g_l[gid] = 0.0f;

    size_t i = gid * 4;
    const float* src;
    __half* dst;
    if (i < ND) {
        src = x + i;
        dst = g_xh + i;
    } else {
        size_t j = i - ND;
        int z = (int)(j / DD);
        size_t o = j - (size_t)z * DD;
        src = ((z == 0) ? Wq : (z == 1) ? Wk : Wv) + o;
        dst = g_Wh[z] + o;
    }
    float4 v = *(const float4*)src;
    ((__half2*)dst)[0] = __floats2half2_rn(v.x, v.y);
    ((__half2*)dst)[1] = __floats2half2_rn(v.z, v.w);
}

// ---------------------------------------------------------------------------
// QKV: out = x @ W^T + b.  z=0: Q; z=1: K; z=2: V transposed.
// grid (128, 8, 3), block 256
// ---------------------------------------------------------------------------
__global__ __launch_bounds__(NTHR, 2) void qkv_mma(
    const float* __restrict__ bq, const float* __restrict__ bk,
    const float* __restrict__ bv)
{
    extern __shared__ char smem[];
    int z = blockIdx.z;
    const float* bias = (z == 0) ? bq : (z == 1) ? bk : bv;

    int tid = threadIdx.x, lane = tid & 31, warp = tid >> 5;
    int wm = warp >> 2, wn = warp & 3;
    int rowBase = blockIdx.x * MT, colBase = blockIdx.y * NTILE;

    float acc[2][4][4] = {};
    gemm_core<DIM / KT>(g_xh, DIM, g_Wh[z], DIM, rowBase, colBase, smem, acc);

    if (z < 2) {
        __half* oh = (z == 0) ? g_Qh : g_Kh;
#pragma unroll
        for (int mi = 0; mi < 2; mi++)
#pragma unroll
            for (int ni = 0; ni < 4; ni++) {
                int r = rowBase + wm * 32 + mi * 16 + (lane >> 2);
                int c = colBase + wn * 32 + ni * 8 + (lane & 3) * 2;
                float b0 = bias[c], b1 = bias[c + 1];
#pragma unroll
                for (int hr = 0; hr < 2; hr++) {
                    size_t o = (size_t)(r + hr * 8) * DIM + c;
                    *(__half2*)(oh + o) = __floats2half2_rn(
                        acc[mi][ni][hr * 2] + b0, acc[mi][ni][hr * 2 + 1] + b1);
                }
            }
    } else {
        // V: transpose via smem, store [dim][token]
        __syncthreads();  // done with mainloop buffers
        __half (*Th)[BPADE] = (__half(*)[BPADE])(smem);   // [128 dims][64 tokens + pad]
#pragma unroll
        for (int mi = 0; mi < 2; mi++)
#pragma unroll
            for (int ni = 0; ni < 4; ni++) {
                int rL = wm * 32 + mi * 16 + (lane >> 2);
                int cL = wn * 32 + ni * 8 + (lane & 3) * 2;
                float b0 = bias[colBase + cL], b1 = bias[colBase + cL + 1];
#pragma unroll
                for (int hr = 0; hr < 2; hr++) {
                    Th[cL][rL + hr * 8]     = __float2half_rn(acc[mi][ni][hr * 2] + b0);
                    Th[cL + 1][rL + hr * 8] = __float2half_rn(acc[mi][ni][hr * 2 + 1] + b1);
                }
            }
        __syncthreads();
#pragma unroll
        for (int j = 0; j < 4; j++) {
            int idx = j * NTHR + tid;
            int cRow = idx >> 3, ch = (idx & 7) * 8;
            float4 vh = *(float4*)&Th[cRow][ch];
            *(float4*)(g_Vth + (size_t)(colBase + cRow) * NTOK + rowBase + ch) = vh;
        }
    }
}

// ---------------------------------------------------------------------------
// Scores fused with exp: P~ = exp((Q K^T)/32 - |dt|/86400), row sums -> g_l.
// grid (128, 64), block 256
// ---------------------------------------------------------------------------
__global__ __launch_bounds__(NTHR, 2) void scores_mma(const float* __restrict__ ts)
{
    extern __shared__ char smem[];
    int tid = threadIdx.x, lane = tid & 31, warp = tid >> 5;
    int wm = warp >> 2, wn = warp & 3;
    int rowBase = blockIdx.x * MT, colBase = blockIdx.y * NTILE;

    float acc[2][4][4] = {};
    gemm_core<DIM / KT>(g_Qh, DIM, g_Kh, DIM, rowBase, colBase, smem, acc);

    const float inv_scale = 1.0f / 32.0f;
    const float inv_T = 1.0f / 86400.0f;

#pragma unroll
    for (int mi = 0; mi < 2; mi++) {
        int r = rowBase + wm * 32 + mi * 16 + (lane >> 2);
        float t_r0 = ts[r], t_r1 = ts[r + 8];
        float sum0 = 0.0f, sum1 = 0.0f;
#pragma unroll
        for (int ni = 0; ni < 4; ni++) {
            int c = colBase + wn * 32 + ni * 8 + (lane & 3) * 2;
            float tc0 = ts[c], tc1 = ts[c + 1];
            float p00 = __expf(acc[mi][ni][0] * inv_scale - fabsf(t_r0 - tc0) * inv_T);
            float p01 = __expf(acc[mi][ni][1] * inv_scale - fabsf(t_r0 - tc1) * inv_T);
            float p10 = __expf(acc[mi][ni][2] * inv_scale - fabsf(t_r1 - tc0) * inv_T);
            float p11 = __expf(acc[mi][ni][3] * inv_scale - fabsf(t_r1 - tc1) * inv_T);
            sum0 += p00 + p01;
            sum1 += p10 + p11;
            *(__half2*)(g_Ph + (size_t)r * NTOK + c) = __floats2half2_rn(p00, p01);
            *(__half2*)(g_Ph + (size_t)(r + 8) * NTOK + c) = __floats2half2_rn(p10, p11);
        }
        sum0 += __shfl_xor_sync(0xffffffff, sum0, 1);
        sum0 += __shfl_xor_sync(0xffffffff, sum0, 2);
        sum1 += __shfl_xor_sync(0xffffffff, sum1, 1);
        sum1 += __shfl_xor_sync(0xffffffff, sum1, 2);
        if ((lane & 3) == 0) {
            atomicAdd(&g_l[r], sum0);
            atomicAdd(&g_l[r + 8], sum1);
        }
    }
}

// ---------------------------------------------------------------------------
// Output: O = diag(1/l) P~ @ V.  grid (128, 8), block 256
// ---------------------------------------------------------------------------
__global__ __launch_bounds__(NTHR, 2) void out_mma(float* __restrict__ O)
{
    extern __shared__ char smem[];
    int tid = threadIdx.x, lane = tid & 31, warp = tid >> 5;
    int wm = warp >> 2, wn = warp & 3;
    int rowBase = blockIdx.x * MT, colBase = blockIdx.y * NTILE;

    float acc[2][4][4] = {};
    gemm_core<NTOK / KT>(g_Ph, NTOK, g_Vth, NTOK, rowBase, colBase, smem, acc);

#pragma unroll
    for (int mi = 0; mi < 2; mi++) {
        int r = rowBase + wm * 32 + mi * 16 + (lane >> 2);
        float i0 = 1.0f / g_l[r], i1 = 1.0f / g_l[r + 8];
#pragma unroll
        for (int ni = 0; ni < 4; ni++) {
            int c = colBase + wn * 32 + ni * 8 + (lane & 3) * 2;
            *(float2*)(O + (size_t)r * DIM + c) =
                make_float2(acc[mi][ni][0] * i0, acc[mi][ni][1] * i0);
            *(float2*)(O + (size_t)(r + 8) * DIM + c) =
                make_float2(acc[mi][ni][2] * i1, acc[mi][ni][3] * i1);
        }
    }
}

// ---------------------------------------------------------------------------
extern "C" void kernel_launch(void* const* d_in, const int* in_sizes, int n_in,
                              void* d_out, int out_size)
{
    const float* x  = (const float*)d_in[0];
    const float* ts = (const float*)d_in[1];
    const float* Wq = (const float*)d_in[2];
    const float* bq = (const float*)d_in[3];
    const float* Wk = (const float*)d_in[4];
    const float* bk = (const float*)d_in[5];
    const float* Wv = (const float*)d_in[6];
    const float* bv = (const float*)d_in[7];
    float* out = (float*)d_out;

    cudaFuncSetAttribute(qkv_mma,    cudaFuncAttributeMaxDynamicSharedMemorySize, SMEM_GEMM);
    cudaFuncSetAttribute(scores_mma, cudaFuncAttributeMaxDynamicSharedMemorySize, SMEM_GEMM);
    cudaFuncSetAttribute(out_mma,    cudaFuncAttributeMaxDynamicSharedMemorySize, SMEM_GEMM);

    const size_t ND = (size_t)NTOK * DIM, DD = (size_t)DIM * DIM;
    int pre_blocks = (int)((ND + 3 * DD) / 4 / 256);
    preprocess_kernel<<<pre_blocks, 256>>>(x, Wq, Wk, Wv);

    qkv_mma<<<dim3(NTOK / MT, DIM / NTILE, 3), NTHR, SMEM_GEMM>>>(bq, bk, bv);
    scores_mma<<<dim3(NTOK / MT, NTOK / NTILE), NTHR, SMEM_GEMM>>>(ts);
    out_mma<<<dim3(NTOK / MT, DIM / NTILE), NTHR, SMEM_GEMM>>>(out);
}

// round 17
// speedup vs baseline: 1.0330x; 1.0026x over previous
#include <cuda_runtime.h>
#include <cuda_fp16.h>
#include <math.h>

#define NTOK 8192
#define DIM  1024
#define MT   64            // A rows per CTA tile
#define NTILE 128          // B rows per CTA tile
#define KT   64            // k-tile depth (fp16 elements)
#define BPADE 72           // smem row stride in elements (144B)
#define ARR_A (MT * BPADE * 2)      // 9216
#define ARR_B (NTILE * BPADE * 2)   // 18432
#define STAGE_BYTES (ARR_A + ARR_B) // 27648
#define NSTAGE 3
#define NTHR 256
#define SMEM_GEMM (NSTAGE * STAGE_BYTES)   // 82944

// ---------------------------------------------------------------------------
// Scratch (static device globals) — all operands single fp16 limb
// ---------------------------------------------------------------------------
__device__ __half g_xh[(size_t)NTOK * DIM];
__device__ __half g_Wh[3][(size_t)DIM * DIM];
__device__ __half g_Qh[(size_t)NTOK * DIM];
__device__ __half g_Kh[(size_t)NTOK * DIM];
__device__ __half g_Vth[(size_t)DIM * NTOK];                      // [dim][token]
__device__ __half g_Ph[(size_t)NTOK * NTOK];                      // P~ = exp(score)
__device__ float g_l[NTOK];                                       // row sums of P~

// ---------------------------------------------------------------------------
// helpers
// ---------------------------------------------------------------------------
__device__ __forceinline__ unsigned smem_u32(const void* p) {
    return (unsigned)__cvta_generic_to_shared(p);
}
__device__ __forceinline__ void cpa16(unsigned s, const void* g) {
    asm volatile("cp.async.cg.shared.global [%0],[%1],16;" :: "r"(s), "l"(g));
}
__device__ __forceinline__ void cpa_commit() {
    asm volatile("cp.async.commit_group;" ::: "memory");
}
__device__ __forceinline__ void cpa_wait0() {
    asm volatile("cp.async.wait_group 0;" ::: "memory");
}
__device__ __forceinline__ void cpa_wait1() {
    asm volatile("cp.async.wait_group 1;" ::: "memory");
}
__device__ __forceinline__ void ldsm4(unsigned r[4], unsigned addr) {
    asm volatile("ldmatrix.sync.aligned.m8n8.x4.shared.b16 {%0,%1,%2,%3},[%4];"
                 : "=r"(r[0]), "=r"(r[1]), "=r"(r[2]), "=r"(r[3]) : "r"(addr));
}
__device__ __forceinline__ void mma_f16(float c[4], const unsigned a[4], const unsigned b[2]) {
    asm volatile("mma.sync.aligned.m16n8k16.row.col.f32.f16.f16.f32 "
                 "{%0,%1,%2,%3},{%4,%5,%6,%7},{%8,%9},{%0,%1,%2,%3};"
                 : "+f"(c[0]), "+f"(c[1]), "+f"(c[2]), "+f"(c[3])
                 : "r"(a[0]), "r"(a[1]), "r"(a[2]), "r"(a[3]), "r"(b[0]), "r"(b[1]));
}

// ---------------------------------------------------------------------------
// fragment load for one k16 slice; warp tile 32x32
// ---------------------------------------------------------------------------
__device__ __forceinline__ void load_frags(
    const char* sb, int kk, int lane, int wm, int wn,
    unsigned ah[2][4], unsigned bh[2][4])
{
    const __half (*Ah)[BPADE] = (const __half(*)[BPADE])(sb);
    const __half (*Bh)[BPADE] = (const __half(*)[BPADE])(sb + ARR_A);

    int arow = (lane & 7) + ((lane >> 3) & 1) * 8;
    int acol = kk + (lane >> 4) * 8;
#pragma unroll
    for (int mi = 0; mi < 2; mi++)
        ldsm4(ah[mi], smem_u32(&Ah[wm * 32 + mi * 16 + arow][acol]));
    int brow = (lane & 7) + ((lane >> 4) & 1) * 8;
    int bcol = kk + ((lane >> 3) & 1) * 8;
#pragma unroll
    for (int p = 0; p < 2; p++)
        ldsm4(bh[p], smem_u32(&Bh[wn * 32 + p * 16 + brow][bcol]));
}

// one 64x128xKT tile, frag double-buffered across the 4 k16 slices
__device__ __forceinline__ void mma_tile(const char* sb, int lane, int wm, int wn,
                                         float acc[2][4][4])
{
    unsigned ah[2][2][4], bh[2][2][4];
    load_frags(sb, 0, lane, wm, wn, ah[0], bh[0]);
#pragma unroll
    for (int s = 0; s < KT / 16; s++) {
        if (s + 1 < KT / 16)
            load_frags(sb, (s + 1) * 16, lane, wm, wn, ah[(s + 1) & 1], bh[(s + 1) & 1]);
#pragma unroll
        for (int mi = 0; mi < 2; mi++)
#pragma unroll
            for (int ni = 0; ni < 4; ni++)
                mma_f16(acc[mi][ni], ah[s & 1][mi], &bh[s & 1][ni >> 1][(ni & 1) * 2]);
    }
}

// ---------------------------------------------------------------------------
// 3-stage pipelined mainloop. A 64 rows at rowBase, B 128 rows at colBase.
// ---------------------------------------------------------------------------
template <int KITERS>
__device__ __forceinline__ void gemm_core(
    const __half* __restrict__ Agh, int sA,
    const __half* __restrict__ Bgh, int sB,
    int rowBase, int colBase, char* smem, float acc[2][4][4])
{
    int tid = threadIdx.x;
    int lane = tid & 31, warp = tid >> 5, wm = warp >> 2, wn = warp & 3;
    unsigned sbase = smem_u32(smem);

#pragma unroll
    for (int pr = 0; pr < 2; pr++) {
        unsigned off = pr * STAGE_BYTES;
        int koff = pr * KT;
#pragma unroll
        for (int j = 0; j < 2; j++) {
            int idx = tid + j * NTHR;
            int row = idx >> 3, col = (idx & 7) * 8;
            cpa16(sbase + off + (row * BPADE + col) * 2,
                  Agh + (size_t)(rowBase + row) * sA + koff + col);
        }
#pragma unroll
        for (int j = 0; j < 4; j++) {
            int idx = tid + j * NTHR;
            int row = idx >> 3, col = (idx & 7) * 8;
            cpa16(sbase + off + ARR_A + (row * BPADE + col) * 2,
                  Bgh + (size_t)(colBase + row) * sB + koff + col);
        }
        cpa_commit();
    }

    for (int it = 0; it < KITERS; it++) {
        if (it == KITERS - 1) cpa_wait0(); else cpa_wait1();
        __syncthreads();
        if (it + 2 < KITERS) {
            unsigned off = ((it + 2) % NSTAGE) * STAGE_BYTES;
            int koff = (it + 2) * KT;
#pragma unroll
            for (int j = 0; j < 2; j++) {
                int idx = tid + j * NTHR;
                int row = idx >> 3, col = (idx & 7) * 8;
                cpa16(sbase + off + (row * BPADE + col) * 2,
                      Agh + (size_t)(rowBase + row) * sA + koff + col);
            }
#pragma unroll
            for (int j = 0; j < 4; j++) {
                int idx = tid + j * NTHR;
                int row = idx >> 3, col = (idx & 7) * 8;
                cpa16(sbase + off + ARR_A + (row * BPADE + col) * 2,
                      Bgh + (size_t)(colBase + row) * sB + koff + col);
            }
            cpa_commit();
        }
        mma_tile(smem + (it % NSTAGE) * STAGE_BYTES, lane, wm, wn, acc);
    }
}

// ---------------------------------------------------------------------------
// fused preprocessing: fp32->fp16 convert of x and the 3 W's, plus g_l zero.
// ---------------------------------------------------------------------------
__global__ __launch_bounds__(256) void preprocess_kernel(
    const float* __restrict__ x,
    const float* __restrict__ Wq, const float* __restrict__ Wk,
    const float* __restrict__ Wv)
{
    const size_t ND = (size_t)NTOK * DIM, DD = (size_t)DIM * DIM;
    size_t gid = (size_t)blockIdx.x * 256 + threadIdx.x;
    if (gid < NTOK) g_l[gid] = 0.0f;

    size_t i = gid * 4;
    const float* src;
    __half* dst;
    if (i < ND) {
        src = x + i;
        dst = g_xh + i;
    } else {
        size_t j = i - ND;
        int z = (int)(j / DD);
        size_t o = j - (size_t)z * DD;
        src = ((z == 0) ? Wq : (z == 1) ? Wk : Wv) + o;
        dst = g_Wh[z] + o;
    }
    float4 v = *(const float4*)src;
    ((__half2*)dst)[0] = __floats2half2_rn(v.x, v.y);
    ((__half2*)dst)[1] = __floats2half2_rn(v.z, v.w);
}

// ---------------------------------------------------------------------------
// QKV: out = x @ W^T + b.  z=0: Q; z=1: K; z=2: V transposed.
// grid (128, 8, 3), block 256
// ---------------------------------------------------------------------------
__global__ __launch_bounds__(NTHR, 2) void qkv_mma(
    const float* __restrict__ bq, const float* __restrict__ bk,
    const float* __restrict__ bv)
{
    extern __shared__ char smem[];
    int z = blockIdx.z;
    const float* bias = (z == 0) ? bq : (z == 1) ? bk : bv;

    int tid = threadIdx.x, lane = tid & 31, warp = tid >> 5;
    int wm = warp >> 2, wn = warp & 3;
    int rowBase = blockIdx.x * MT, colBase = blockIdx.y * NTILE;

    float acc[2][4][4] = {};
    gemm_core<DIM / KT>(g_xh, DIM, g_Wh[z], DIM, rowBase, colBase, smem, acc);

    if (z < 2) {
        __half* oh = (z == 0) ? g_Qh : g_Kh;
#pragma unroll
        for (int mi = 0; mi < 2; mi++)
#pragma unroll
            for (int ni = 0; ni < 4; ni++) {
                int r = rowBase + wm * 32 + mi * 16 + (lane >> 2);
                int c = colBase + wn * 32 + ni * 8 + (lane & 3) * 2;
                float b0 = bias[c], b1 = bias[c + 1];
#pragma unroll
                for (int hr = 0; hr < 2; hr++) {
                    size_t o = (size_t)(r + hr * 8) * DIM + c;
                    *(__half2*)(oh + o) = __floats2half2_rn(
                        acc[mi][ni][hr * 2] + b0, acc[mi][ni][hr * 2 + 1] + b1);
                }
            }
    } else {
        // V: transpose via smem, store [dim][token]
        __syncthreads();  // done with mainloop buffers
        __half (*Th)[BPADE] = (__half(*)[BPADE])(smem);   // [128 dims][64 tokens + pad]
#pragma unroll
        for (int mi = 0; mi < 2; mi++)
#pragma unroll
            for (int ni = 0; ni < 4; ni++) {
                int rL = wm * 32 + mi * 16 + (lane >> 2);
                int cL = wn * 32 + ni * 8 + (lane & 3) * 2;
                float b0 = bias[colBase + cL], b1 = bias[colBase + cL + 1];
#pragma unroll
                for (int hr = 0; hr < 2; hr++) {
                    Th[cL][rL + hr * 8]     = __float2half_rn(acc[mi][ni][hr * 2] + b0);
                    Th[cL + 1][rL + hr * 8] = __float2half_rn(acc[mi][ni][hr * 2 + 1] + b1);
                }
            }
        __syncthreads();
#pragma unroll
        for (int j = 0; j < 4; j++) {
            int idx = j * NTHR + tid;
            int cRow = idx >> 3, ch = (idx & 7) * 8;
            float4 vh = *(float4*)&Th[cRow][ch];
            *(float4*)(g_Vth + (size_t)(colBase + cRow) * NTOK + rowBase + ch) = vh;
        }
    }
}

// ---------------------------------------------------------------------------
// Scores fused with exp: P~ = exp((Q K^T)/32 - |dt|/86400), row sums -> g_l.
// grid (128, 64), block 256
// ---------------------------------------------------------------------------
__global__ __launch_bounds__(NTHR, 2) void scores_mma(const float* __restrict__ ts)
{
    extern __shared__ char smem[];
    int tid = threadIdx.x, lane = tid & 31, warp = tid >> 5;
    int wm = warp >> 2, wn = warp & 3;
    int rowBase = blockIdx.x * MT, colBase = blockIdx.y * NTILE;

    float acc[2][4][4] = {};
    gemm_core<DIM / KT>(g_Qh, DIM, g_Kh, DIM, rowBase, colBase, smem, acc);

    const float inv_scale = 1.0f / 32.0f;
    const float inv_T = 1.0f / 86400.0f;

#pragma unroll
    for (int mi = 0; mi < 2; mi++) {
        int r = rowBase + wm * 32 + mi * 16 + (lane >> 2);
        float t_r0 = ts[r], t_r1 = ts[r + 8];
        float sum0 = 0.0f, sum1 = 0.0f;
#pragma unroll
        for (int ni = 0; ni < 4; ni++) {
            int c = colBase + wn * 32 + ni * 8 + (lane & 3) * 2;
            float tc0 = ts[c], tc1 = ts[c + 1];
            float p00 = __expf(acc[mi][ni][0] * inv_scale - fabsf(t_r0 - tc0) * inv_T);
            float p01 = __expf(acc[mi][ni][1] * inv_scale - fabsf(t_r0 - tc1) * inv_T);
            float p10 = __expf(acc[mi][ni][2] * inv_scale - fabsf(t_r1 - tc0) * inv_T);
            float p11 = __expf(acc[mi][ni][3] * inv_scale - fabsf(t_r1 - tc1) * inv_T);
            sum0 += p00 + p01;
            sum1 += p10 + p11;
            *(__half2*)(g_Ph + (size_t)r * NTOK + c) = __floats2half2_rn(p00, p01);
            *(__half2*)(g_Ph + (size_t)(r + 8) * NTOK + c) = __floats2half2_rn(p10, p11);
        }
        sum0 += __shfl_xor_sync(0xffffffff, sum0, 1);
        sum0 += __shfl_xor_sync(0xffffffff, sum0, 2);
        sum1 += __shfl_xor_sync(0xffffffff, sum1, 1);
        sum1 += __shfl_xor_sync(0xffffffff, sum1, 2);
        if ((lane & 3) == 0) {
            atomicAdd(&g_l[r], sum0);
            atomicAdd(&g_l[r + 8], sum1);
        }
    }
}

// ---------------------------------------------------------------------------
// Output: O = diag(1/l) P~ @ V.  grid (8, 128): x = col tile (fast), y = row
// tile, so the 8 CTAs sharing one P~ row-slice are launch-adjacent and the
// slice is served from L2 after one DRAM fetch.  block 256
// ---------------------------------------------------------------------------
__global__ __launch_bounds__(NTHR, 2) void out_mma(float* __restrict__ O)
{
    extern __shared__ char smem[];
    int tid = threadIdx.x, lane = tid & 31, warp = tid >> 5;
    int wm = warp >> 2, wn = warp & 3;
    int rowBase = blockIdx.y * MT, colBase = blockIdx.x * NTILE;

    float acc[2][4][4] = {};
    gemm_core<NTOK / KT>(g_Ph, NTOK, g_Vth, NTOK, rowBase, colBase, smem, acc);

#pragma unroll
    for (int mi = 0; mi < 2; mi++) {
        int r = rowBase + wm * 32 + mi * 16 + (lane >> 2);
        float i0 = 1.0f / g_l[r], i1 = 1.0f / g_l[r + 8];
#pragma unroll
        for (int ni = 0; ni < 4; ni++) {
            int c = colBase + wn * 32 + ni * 8 + (lane & 3) * 2;
            *(float2*)(O + (size_t)r * DIM + c) =
                make_float2(acc[mi][ni][0] * i0, acc[mi][ni][1] * i0);
            *(float2*)(O + (size_t)(r + 8) * DIM + c) =
                make_float2(acc[mi][ni][2] * i1, acc[mi][ni][3] * i1);
        }
    }
}

// ---------------------------------------------------------------------------
extern "C" void kernel_launch(void* const* d_in, const int* in_sizes, int n_in,
                              void* d_out, int out_size)
{
    const float* x  = (const float*)d_in[0];
    const float* ts = (const float*)d_in[1];
    const float* Wq = (const float*)d_in[2];
    const float* bq = (const float*)d_in[3];
    const float* Wk = (const float*)d_in[4];
    const float* bk = (const float*)d_in[5];
    const float* Wv = (const float*)d_in[6];
    const float* bv = (const float*)d_in[7];
    float* out = (float*)d_out;

    cudaFuncSetAttribute(qkv_mma,    cudaFuncAttributeMaxDynamicSharedMemorySize, SMEM_GEMM);
    cudaFuncSetAttribute(scores_mma, cudaFuncAttributeMaxDynamicSharedMemorySize, SMEM_GEMM);
    cudaFuncSetAttribute(out_mma,    cudaFuncAttributeMaxDynamicSharedMemorySize, SMEM_GEMM);

    const size_t ND = (size_t)NTOK * DIM, DD = (size_t)DIM * DIM;
    int pre_blocks = (int)((ND + 3 * DD) / 4 / 256);
    preprocess_kernel<<<pre_blocks, 256>>>(x, Wq, Wk, Wv);

    qkv_mma<<<dim3(NTOK / MT, DIM / NTILE, 3), NTHR, SMEM_GEMM>>>(bq, bk, bv);
    scores_mma<<<dim3(NTOK / MT, NTOK / NTILE), NTHR, SMEM_GEMM>>>(ts);
    out_mma<<<dim3(DIM / NTILE, NTOK / MT), NTHR, SMEM_GEMM>>>(out);
}